// round 4
// baseline (speedup 1.0000x reference)
#include <cuda_runtime.h>
#include <cuda_bf16.h>
#include <cstdint>

// Shapes fixed by dataset: L_F=32, HOP=16, DELTA=3, L_S=96, COND=32, GH=64, B=128, T=48000
// Nf = 2999, Ns = 999
#define BSZ    128
#define NS_MAX 999
#define NF_MAX 2999

typedef unsigned long long u64t;

// ---------------- packed f32x2 helpers (sm_103a FFMA2 path) ----------------
__device__ __forceinline__ u64t ffma2(u64t a, u64t b, u64t c) {
    u64t d; asm("fma.rn.f32x2 %0, %1, %2, %3;" : "=l"(d) : "l"(a), "l"(b), "l"(c)); return d;
}
__device__ __forceinline__ u64t fadd2(u64t a, u64t b) {
    u64t d; asm("add.rn.f32x2 %0, %1, %2;" : "=l"(d) : "l"(a), "l"(b)); return d;
}
__device__ __forceinline__ u64t fpack2(float lo, float hi) {
    u64t d; asm("mov.b64 %0, {%1, %2};" : "=l"(d) : "f"(lo), "f"(hi)); return d;
}
__device__ __forceinline__ float2 funpack2(u64t v) {
    float2 f; asm("mov.b64 {%0, %1}, %2;" : "=f"(f.x), "=f"(f.y) : "l"(v)); return f;
}
__device__ __forceinline__ float hsum2(u64t v) { float2 f = funpack2(v); return f.x + f.y; }

// ---------------- scratch (device globals; no allocations allowed) ----------
__device__ float g_gi[(size_t)BSZ * NS_MAX * 192];
__device__ float g_hs[(size_t)BSZ * NS_MAX * 64];
__device__ float g_cs[(size_t)BSZ * NS_MAX * 32];
__device__ float g_y [(size_t)BSZ * NF_MAX * 32];

// =====================================================================
// Kernel A: gi[b][s][j] = b_ih[j] + W_ih[j,:] . x[b, s*48 : s*48+96]
// 2 consecutive s per thread (windows overlap 48 samples -> 144 feature
// floats in regs). Per jj: 24 broadcast LDS.128 feed 96 FFMA2 (4:1).
// Outputs staged through padded transpose tile -> coalesced stores.
// =====================================================================
__global__ void __launch_bounds__(128) gi_kernel(const float* __restrict__ x,
                                                 const float* __restrict__ W_ih,
                                                 const float* __restrict__ b_ih,
                                                 int T, int Ns) {
    __shared__ __align__(16) float Wc[32 * 96];      // 12.3 KB
    __shared__ float tile[32 * 257];                 // 32.9 KB (256 s-cols + pad)
    __shared__ float bsh[192];

    const int b   = blockIdx.y;
    const int s0b = blockIdx.x * 256;                // block covers 256 s
    const int tid = threadIdx.x;
    const int sA  = s0b + 2 * tid;                   // this thread's two s
    const int sB  = sA + 1;
    const bool vA = (sA < Ns);
    const bool vB = (sB < Ns);

    for (int i = tid; i < 192; i += 128) bsh[i] = b_ih[i];

    // 144-float shared window -> 72 packed pairs
    u64t f2[72];
    {
        const float4* xp = reinterpret_cast<const float4*>(x + (size_t)b * T + (size_t)sA * 48);
        #pragma unroll
        for (int q = 0; q < 24; q++) {               // first 96 floats (window A)
            float4 v = vA ? xp[q] : make_float4(0.f, 0.f, 0.f, 0.f);
            f2[3*q+0] = fpack2(v.x, v.y);            // NOTE: 2 pairs per float4
            f2[3*q+1] = 0ULL;                        // placeholder fixed below
            (void)0;
        }
        // redo cleanly: 36 float4 total, guarded in two ranges
        #pragma unroll
        for (int q = 0; q < 36; q++) {
            bool ok = (q < 24) ? vA : vB;            // floats [96..144) belong to window B only
            float4 v = ok ? xp[q] : make_float4(0.f, 0.f, 0.f, 0.f);
            f2[2*q]   = fpack2(v.x, v.y);
            f2[2*q+1] = fpack2(v.z, v.w);
        }
    }

    for (int jc = 0; jc < 6; jc++) {
        __syncthreads();                             // prev tile fully consumed
        const float* wsrc = W_ih + jc * 32 * 96;
        for (int i = tid; i < 32 * 96; i += 128) Wc[i] = wsrc[i];
        __syncthreads();

        #pragma unroll 1
        for (int jj = 0; jj < 32; jj++) {
            const ulonglong2* wv = reinterpret_cast<const ulonglong2*>(&Wc[jj * 96]);
            u64t a0=0ULL,a1=0ULL,a2=0ULL,a3=0ULL;    // window A (f2[0..47])
            u64t c0=0ULL,c1=0ULL,c2=0ULL,c3=0ULL;    // window B (f2[24..71])
            #pragma unroll
            for (int p = 0; p < 24; p++) {           // 1 LDS.128 -> 4 FFMA2
                ulonglong2 w = wv[p];
                if (p & 1) {
                    a2 = ffma2(w.x, f2[2*p],      a2); a3 = ffma2(w.y, f2[2*p+1],      a3);
                    c2 = ffma2(w.x, f2[24+2*p],   c2); c3 = ffma2(w.y, f2[24+2*p+1],   c3);
                } else {
                    a0 = ffma2(w.x, f2[2*p],      a0); a1 = ffma2(w.y, f2[2*p+1],      a1);
                    c0 = ffma2(w.x, f2[24+2*p],   c0); c1 = ffma2(w.y, f2[24+2*p+1],   c1);
                }
            }
            const float bb = bsh[jc * 32 + jj];
            tile[jj * 257 + tid      ] = hsum2(fadd2(fadd2(a0,a1), fadd2(a2,a3))) + bb; // col tid   <-> s = s0b+2*tid
            tile[jj * 257 + 128 + tid] = hsum2(fadd2(fadd2(c0,c1), fadd2(c2,c3))) + bb; // col 128+m <-> s = s0b+2*tid+1
        }
        __syncthreads();                             // tile complete before gather-store

        #pragma unroll
        for (int it = 0; it < 16; it++) {
            int q  = tid + it * 128;                 // float4 index in [0, 2048)
            int j0 = (q & 7) * 4;
            int sl = q >> 3;                         // s-local 0..255
            if (s0b + sl < Ns) {
                int col = (sl >> 1) + ((sl & 1) << 7);
                float4 v;
                v.x = tile[(j0    ) * 257 + col];
                v.y = tile[(j0 + 1) * 257 + col];
                v.z = tile[(j0 + 2) * 257 + col];
                v.w = tile[(j0 + 3) * 257 + col];
                *reinterpret_cast<float4*>(&g_gi[((size_t)b * Ns + s0b + sl) * 192 + jc * 32 + j0]) = v;
            }
        }
    }
}

// =====================================================================
// Kernel B: GRU recurrence. 1 block / batch row, 192 threads.
// Row j of W_hh register-resident; depth-4 prefetch ring on the gi stream
// (covers ~4 step-latencies of DRAM latency).
// =====================================================================
__global__ void __launch_bounds__(192, 1) gru_kernel(const float* __restrict__ W_hh,
                                                     const float* __restrict__ b_hh,
                                                     int Ns) {
    __shared__ __align__(16) float h_sh[64];
    __shared__ float gh_sh[192];
    __shared__ float gi_sh[192];

    const int b = blockIdx.x;
    const int j = threadIdx.x;

    u64t wr[32];
    {
        const ulonglong2* wsrc = reinterpret_cast<const ulonglong2*>(W_hh + j * 64);
        #pragma unroll
        for (int p = 0; p < 16; p++) { ulonglong2 v = wsrc[p]; wr[2*p] = v.x; wr[2*p+1] = v.y; }
    }
    const float bj = b_hh[j];
    if (j < 64) h_sh[j] = 0.f;
    __syncthreads();

    const float* gib = g_gi + (size_t)b * Ns * 192;
    float*       hsb = g_hs + (size_t)b * Ns * 64;

    float gpre[4];
    #pragma unroll
    for (int d = 0; d < 4; d++) gpre[d] = (d < Ns) ? __ldg(&gib[d * 192 + j]) : 0.f;

    for (int t = 0; t < Ns; t++) {
        const float gv = gpre[t & 3];
        const int tp = t + 4;
        if (tp < Ns) gpre[t & 3] = __ldg(&gib[tp * 192 + j]);   // independent, issued early

        const ulonglong2* hv = reinterpret_cast<const ulonglong2*>(h_sh);
        u64t a0 = 0ULL, a1 = 0ULL, a2 = 0ULL, a3 = 0ULL;
        #pragma unroll
        for (int p = 0; p < 16; p++) {
            ulonglong2 h4 = hv[p];
            if (p & 1) { a2 = ffma2(wr[2*p], h4.x, a2); a3 = ffma2(wr[2*p+1], h4.y, a3); }
            else       { a0 = ffma2(wr[2*p], h4.x, a0); a1 = ffma2(wr[2*p+1], h4.y, a1); }
        }
        gh_sh[j] = hsum2(fadd2(fadd2(a0, a1), fadd2(a2, a3))) + bj;
        gi_sh[j] = gv;
        __syncthreads();

        if (j < 64) {
            const float r  = 1.f / (1.f + __expf(-(gi_sh[j]       + gh_sh[j]      )));
            const float z  = 1.f / (1.f + __expf(-(gi_sh[j + 64]  + gh_sh[j + 64] )));
            const float n  = tanhf(gi_sh[j + 128] + r * gh_sh[j + 128]);
            const float hn = (1.f - z) * n + z * h_sh[j];
            h_sh[j] = hn;
            hsb[t * 64 + j] = hn;
        }
        __syncthreads();
    }
}

// =====================================================================
// Kernel B2: c_s = hs @ W_cs.T + b_cs
// =====================================================================
__global__ void __launch_bounds__(256) cs_kernel(const float* __restrict__ W_cs,
                                                 const float* __restrict__ b_cs,
                                                 int Ns) {
    __shared__ float wsh[64 * 32];   // [k][i]
    __shared__ float hsh[8 * 64];

    const int b  = blockIdx.y;
    const int t0 = blockIdx.x * 8;
    const int tid = threadIdx.x;

    for (int i = tid; i < 2048; i += 256) {
        const int k = i >> 5, ii = i & 31;
        wsh[i] = W_cs[ii * 64 + k];
    }
    const int nvalid = min(8, Ns - t0);
    for (int i = tid; i < nvalid * 64; i += 256)
        hsh[i] = g_hs[((size_t)b * Ns + t0) * 64 + i];
    __syncthreads();

    const int tl = tid >> 5, ii = tid & 31;
    if (tl < nvalid) {
        float acc = b_cs[ii];
        #pragma unroll
        for (int k = 0; k < 64; k++)
            acc = fmaf(wsh[k * 32 + ii], hsh[tl * 64 + k], acc);
        g_cs[((size_t)b * Ns + (t0 + tl)) * 32 + ii] = acc;
    }
}

// =====================================================================
// Kernel C: fast path, 2 consecutive frames per thread (share 16 x-samples).
// Per jj: 24 broadcast LDS.128 feed 96 FFMA2 (4:1). Stage-2 fused rank-1.
// =====================================================================
__global__ void __launch_bounds__(128) fast_kernel(const float* __restrict__ x,
                                                   const float* __restrict__ W1,
                                                   const float* __restrict__ b1,
                                                   const float* __restrict__ W2,
                                                   const float* __restrict__ b2,
                                                   int T, int Nf, int Ns) {
    __shared__ __align__(16) float W1sh[64 * 64];   // [j][k]
    __shared__ __align__(16) float W2T[64 * 32];    // [j][i]
    __shared__ float b1sh[64];
    __shared__ u64t  b2sh[16];

    const int b   = blockIdx.y;
    const int tid = threadIdx.x;
    const int n0  = (blockIdx.x * 128 + tid) * 2;
    const int n1  = n0 + 1;

    for (int i = tid; i < 4096; i += 128) W1sh[i] = W1[i];
    for (int i = tid; i < 2048; i += 128) { int jj = i >> 5, ii = i & 31; W2T[i] = W2[ii * 64 + jj]; }
    if (tid < 64) b1sh[tid] = b1[tid];
    if (tid < 16) b2sh[tid] = fpack2(b2[2 * tid], b2[2 * tid + 1]);
    __syncthreads();

    if (n0 >= Nf) return;
    const bool v1 = (n1 < Nf);

    // x window: 48 floats covering both frames (A: [0..31], B: [16..47])
    u64t xf[24];
    {
        const float4* xp = reinterpret_cast<const float4*>(x + (size_t)b * T + (size_t)n0 * 16);
        #pragma unroll
        for (int q = 0; q < 12; q++) {
            float4 v = (q < 8 || v1) ? xp[q] : make_float4(0.f, 0.f, 0.f, 0.f);
            xf[2*q]   = fpack2(v.x, v.y);
            xf[2*q+1] = fpack2(v.z, v.w);
        }
    }
    u64t cf0[16], cf1[16];
    {
        int cn0 = n0 / 3 - 1; if (cn0 < 0) cn0 = 0;
        int cn1 = v1 ? (n1 / 3 - 1) : cn0; if (cn1 < 0) cn1 = 0;
        const ulonglong2* cp0 = reinterpret_cast<const ulonglong2*>(g_cs + ((size_t)b * Ns + cn0) * 32);
        const ulonglong2* cp1 = reinterpret_cast<const ulonglong2*>(g_cs + ((size_t)b * Ns + cn1) * 32);
        #pragma unroll
        for (int q = 0; q < 8; q++) {
            ulonglong2 u = cp0[q]; cf0[2*q] = u.x; cf0[2*q+1] = u.y;
            ulonglong2 w = cp1[q]; cf1[2*q] = w.x; cf1[2*q+1] = w.y;
        }
    }

    u64t ya[16], yb[16];
    #pragma unroll
    for (int i = 0; i < 16; i++) { ya[i] = 0ULL; yb[i] = 0ULL; }

    #pragma unroll 1
    for (int jj = 0; jj < 64; jj++) {
        const ulonglong2* w1v = reinterpret_cast<const ulonglong2*>(&W1sh[jj * 64]);
        u64t a0=0ULL,a1=0ULL,a2=0ULL,a3=0ULL;   // frame A
        u64t c0=0ULL,c1=0ULL,c2=0ULL,c3=0ULL;   // frame B
        #pragma unroll
        for (int p = 0; p < 8; p++) {           // x half: A uses xf[0..15], B uses xf[8..23]
            ulonglong2 w = w1v[p];
            a0 = ffma2(w.x, xf[2*p],     a0); a1 = ffma2(w.y, xf[2*p+1],     a1);
            c0 = ffma2(w.x, xf[8+2*p],   c0); c1 = ffma2(w.y, xf[8+2*p+1],   c1);
        }
        #pragma unroll
        for (int p = 0; p < 8; p++) {           // c half
            ulonglong2 w = w1v[8 + p];
            a2 = ffma2(w.x, cf0[2*p], a2); a3 = ffma2(w.y, cf0[2*p+1], a3);
            c2 = ffma2(w.x, cf1[2*p], c2); c3 = ffma2(w.y, cf1[2*p+1], c3);
        }
        float hA = fmaxf(hsum2(fadd2(fadd2(a0,a1), fadd2(a2,a3))) + b1sh[jj], 0.f);
        float hB = fmaxf(hsum2(fadd2(fadd2(c0,c1), fadd2(c2,c3))) + b1sh[jj], 0.f);
        u64t hA2 = fpack2(hA, hA);
        u64t hB2 = fpack2(hB, hB);
        const ulonglong2* w2v = reinterpret_cast<const ulonglong2*>(&W2T[jj * 32]);
        #pragma unroll
        for (int p = 0; p < 8; p++) {           // fused stage-2 rank-1 update (both frames)
            ulonglong2 w = w2v[p];
            ya[2*p] = ffma2(w.x, hA2, ya[2*p]); ya[2*p+1] = ffma2(w.y, hA2, ya[2*p+1]);
            yb[2*p] = ffma2(w.x, hB2, yb[2*p]); yb[2*p+1] = ffma2(w.y, hB2, yb[2*p+1]);
        }
    }

    {
        float4* yo = reinterpret_cast<float4*>(&g_y[((size_t)b * Nf + n0) * 32]);
        #pragma unroll
        for (int p = 0; p < 8; p++) {
            float2 va = funpack2(fadd2(ya[2*p],     b2sh[2*p]));
            float2 vb = funpack2(fadd2(ya[2*p + 1], b2sh[2*p + 1]));
            yo[p] = make_float4(va.x, va.y, vb.x, vb.y);
        }
        if (v1) {
            float4* yo1 = reinterpret_cast<float4*>(&g_y[((size_t)b * Nf + n1) * 32]);
            #pragma unroll
            for (int p = 0; p < 8; p++) {
                float2 va = funpack2(fadd2(yb[2*p],     b2sh[2*p]));
                float2 vb = funpack2(fadd2(yb[2*p + 1], b2sh[2*p + 1]));
                yo1[p] = make_float4(va.x, va.y, vb.x, vb.y);
            }
        }
    }
}

// =====================================================================
// Kernel D: overlap-add as gather (each sample covered by <=2 frames).
// =====================================================================
__global__ void __launch_bounds__(256) gather_kernel(float* __restrict__ out,
                                                     int T, int Nf) {
    const int idx = blockIdx.x * blockDim.x + threadIdx.x;
    const int total = BSZ * T;
    if (idx >= total) return;
    const int b = idx / T, t = idx % T;
    const int n0 = t >> 4, r = t & 15;
    const float* yb = g_y + (size_t)b * Nf * 32;
    float v = 0.f;
    if (n0 < Nf)                 v += yb[n0 * 32 + r];
    if (n0 >= 1 && n0 - 1 < Nf)  v += yb[(n0 - 1) * 32 + 16 + r];
    out[idx] = v;
}

// =====================================================================
extern "C" void kernel_launch(void* const* d_in, const int* in_sizes, int n_in,
                              void* d_out, int out_size) {
    const float* x    = (const float*)d_in[0];
    const float* W_ih = (const float*)d_in[1];
    const float* W_hh = (const float*)d_in[2];
    const float* b_ih = (const float*)d_in[3];
    const float* b_hh = (const float*)d_in[4];
    const float* W_cs = (const float*)d_in[5];
    const float* b_cs = (const float*)d_in[6];
    const float* W1   = (const float*)d_in[7];
    const float* b1   = (const float*)d_in[8];
    const float* W2   = (const float*)d_in[9];
    const float* b2   = (const float*)d_in[10];
    float* out = (float*)d_out;

    const int T  = in_sizes[0] / BSZ;
    const int Nf = (T - 32) / 16 + 1;
    const int Ns = (T - 96) / 48 + 1;

    gi_kernel    <<<dim3((Ns + 255) / 256, BSZ), 128>>>(x, W_ih, b_ih, T, Ns);
    gru_kernel   <<<BSZ, 192>>>(W_hh, b_hh, Ns);
    cs_kernel    <<<dim3((Ns + 7) / 8, BSZ), 256>>>(W_cs, b_cs, Ns);
    fast_kernel  <<<dim3((Nf + 255) / 256, BSZ), 128>>>(x, W1, b1, W2, b2, T, Nf, Ns);
    gather_kernel<<<(BSZ * T + 255) / 256, 256>>>(out, T, Nf);
}

// round 6
// speedup vs baseline: 1.4267x; 1.4267x over previous
#include <cuda_runtime.h>
#include <cuda_bf16.h>
#include <cstdint>

// Shapes fixed by dataset: L_F=32, HOP=16, DELTA=3, L_S=96, COND=32, GH=64, B=128, T=48000
// Nf = 2999, Ns = 999
#define BSZ    128
#define NS_MAX 999
#define NF_MAX 2999

typedef unsigned long long u64t;

// ---------------- packed f32x2 helpers (sm_103a FFMA2 path) ----------------
__device__ __forceinline__ u64t ffma2(u64t a, u64t b, u64t c) {
    u64t d; asm("fma.rn.f32x2 %0, %1, %2, %3;" : "=l"(d) : "l"(a), "l"(b), "l"(c)); return d;
}
__device__ __forceinline__ u64t fadd2(u64t a, u64t b) {
    u64t d; asm("add.rn.f32x2 %0, %1, %2;" : "=l"(d) : "l"(a), "l"(b)); return d;
}
__device__ __forceinline__ u64t fpack2(float lo, float hi) {
    u64t d; asm("mov.b64 %0, {%1, %2};" : "=l"(d) : "f"(lo), "f"(hi)); return d;
}
__device__ __forceinline__ float2 funpack2(u64t v) {
    float2 f; asm("mov.b64 {%0, %1}, %2;" : "=f"(f.x), "=f"(f.y) : "l"(v)); return f;
}
__device__ __forceinline__ float hsum2(u64t v) { float2 f = funpack2(v); return f.x + f.y; }

// ---------------- fast transcendentals (MUFU; err ~1e-7, budget 1e-3) ------
__device__ __forceinline__ float fast_ex2(float x) {
    float y; asm("ex2.approx.f32 %0, %1;" : "=f"(y) : "f"(x)); return y;
}
__device__ __forceinline__ float fast_rcp(float x) {
    float y; asm("rcp.approx.f32 %0, %1;" : "=f"(y) : "f"(x)); return y;
}
__device__ __forceinline__ float fast_sigmoid(float v) {      // 1/(1+e^-v)
    return fast_rcp(1.f + fast_ex2(-1.4426950408889634f * v));
}
__device__ __forceinline__ float fast_tanh(float v) {         // 2*sigm(2v)-1
    return 2.f * fast_rcp(1.f + fast_ex2(-2.8853900817779268f * v)) - 1.f;
}

// ---------------- scratch (device globals; no allocations allowed) ----------
__device__ float g_gi[(size_t)BSZ * NS_MAX * 192];
__device__ float g_cs[(size_t)BSZ * NS_MAX * 32];
__device__ float g_y [(size_t)BSZ * NF_MAX * 32];

// =====================================================================
// Kernel A (R2 form, known good): gi[b][s][j] = b_ih[j] + W_ih[j,:].x[...]
// Thread-per-s, 96 feature floats in regs, W chunk in shared (broadcast
// LDS.128), transpose tile -> coalesced stores.
// =====================================================================
__global__ void __launch_bounds__(128) gi_kernel(const float* __restrict__ x,
                                                 const float* __restrict__ W_ih,
                                                 const float* __restrict__ b_ih,
                                                 int T, int Ns) {
    __shared__ __align__(16) float Wc[32 * 96];     // 12.3 KB
    __shared__ float tile[32 * 129];                // 16.5 KB
    __shared__ float bsh[192];

    const int b   = blockIdx.y;
    const int s0  = blockIdx.x * 128;
    const int tid = threadIdx.x;
    const int s   = s0 + tid;
    const bool valid = (s < Ns);

    for (int i = tid; i < 192; i += 128) bsh[i] = b_ih[i];

    u64t f2[48];
    if (valid) {
        const ulonglong2* xp = reinterpret_cast<const ulonglong2*>(x + (size_t)b * T + (size_t)s * 48);
        #pragma unroll
        for (int q = 0; q < 24; q++) { ulonglong2 v = xp[q]; f2[2*q] = v.x; f2[2*q+1] = v.y; }
    } else {
        #pragma unroll
        for (int i = 0; i < 48; i++) f2[i] = 0ULL;
    }

    int nv = Ns - s0; if (nv > 128) nv = 128;

    for (int jc = 0; jc < 6; jc++) {
        __syncthreads();
        const float* wsrc = W_ih + jc * 32 * 96;
        for (int i = tid; i < 32 * 96; i += 128) Wc[i] = wsrc[i];
        __syncthreads();

        #pragma unroll 1
        for (int jj = 0; jj < 32; jj++) {
            const ulonglong2* wv = reinterpret_cast<const ulonglong2*>(&Wc[jj * 96]);
            u64t a0 = 0ULL, a1 = 0ULL, a2 = 0ULL, a3 = 0ULL;
            #pragma unroll
            for (int p = 0; p < 24; p++) {
                ulonglong2 w = wv[p];
                if (p & 1) { a2 = ffma2(w.x, f2[2*p], a2); a3 = ffma2(w.y, f2[2*p+1], a3); }
                else       { a0 = ffma2(w.x, f2[2*p], a0); a1 = ffma2(w.y, f2[2*p+1], a1); }
            }
            tile[jj * 129 + tid] = hsum2(fadd2(fadd2(a0, a1), fadd2(a2, a3))) + bsh[jc * 32 + jj];
        }
        __syncthreads();

        #pragma unroll
        for (int it = 0; it < 8; it++) {
            int q  = tid + it * 128;
            int j0 = (q & 7) * 4;
            int sl = q >> 3;
            if (sl < nv) {
                float4 v;
                v.x = tile[(j0    ) * 129 + sl];
                v.y = tile[(j0 + 1) * 129 + sl];
                v.z = tile[(j0 + 2) * 129 + sl];
                v.w = tile[(j0 + 3) * 129 + sl];
                *reinterpret_cast<float4*>(&g_gi[((size_t)b * Ns + s0 + sl) * 192 + jc * 32 + j0]) = v;
            }
        }
    }
}

// =====================================================================
// Kernel B: GRU recurrence with fused c_s projection.
// 224 threads: j<192 -> gate row j (W_hh register-resident);
//              j>=192 -> c_s row j-192 (W_cs register-resident), computed
//              on the PREVIOUS h during the dot phase (perfect overlap).
// g_hs eliminated entirely. Fast MUFU sigmoid/tanh on the critical path.
// =====================================================================
__global__ void __launch_bounds__(224, 1) gru_kernel(const float* __restrict__ W_hh,
                                                     const float* __restrict__ b_hh,
                                                     const float* __restrict__ W_cs,
                                                     const float* __restrict__ b_cs,
                                                     int Ns) {
    __shared__ __align__(16) float h_sh[64];
    __shared__ float gh_sh[192];
    __shared__ float gi_sh[192];

    const int b = blockIdx.x;
    const int j = threadIdx.x;
    const bool is_gate = (j < 192);

    u64t wr[32];
    float bj;
    {
        const float* wsrc_f = is_gate ? (W_hh + j * 64) : (W_cs + (j - 192) * 64);
        const ulonglong2* wsrc = reinterpret_cast<const ulonglong2*>(wsrc_f);
        #pragma unroll
        for (int p = 0; p < 16; p++) { ulonglong2 v = wsrc[p]; wr[2*p] = v.x; wr[2*p+1] = v.y; }
        bj = is_gate ? b_hh[j] : b_cs[j - 192];
    }
    if (j < 64) h_sh[j] = 0.f;
    __syncthreads();

    const float* gib = g_gi + (size_t)b * Ns * 192;
    float*       csb = g_cs + (size_t)b * Ns * 32;

    float gv = is_gate ? __ldg(&gib[j]) : 0.f;
    for (int t = 0; t < Ns; t++) {
        const float gv_next = (is_gate && t + 1 < Ns) ? __ldg(&gib[(t + 1) * 192 + j]) : 0.f;

        // dot over h_sh (= hs[t-1])
        const ulonglong2* hv = reinterpret_cast<const ulonglong2*>(h_sh);
        u64t a0 = 0ULL, a1 = 0ULL, a2 = 0ULL, a3 = 0ULL;
        #pragma unroll
        for (int p = 0; p < 16; p++) {
            ulonglong2 h4 = hv[p];
            if (p & 1) { a2 = ffma2(wr[2*p], h4.x, a2); a3 = ffma2(wr[2*p+1], h4.y, a3); }
            else       { a0 = ffma2(wr[2*p], h4.x, a0); a1 = ffma2(wr[2*p+1], h4.y, a1); }
        }
        const float acc = hsum2(fadd2(fadd2(a0, a1), fadd2(a2, a3))) + bj;

        if (is_gate) { gh_sh[j] = acc; gi_sh[j] = gv; }
        else if (t > 0) csb[(size_t)(t - 1) * 32 + (j - 192)] = acc;   // c_s[t-1]
        __syncthreads();

        if (j < 64) {
            const float r  = fast_sigmoid(gi_sh[j]       + gh_sh[j]      );
            const float z  = fast_sigmoid(gi_sh[j + 64]  + gh_sh[j + 64] );
            const float n  = fast_tanh   (gi_sh[j + 128] + r * gh_sh[j + 128]);
            h_sh[j] = (1.f - z) * n + z * h_sh[j];
        }
        __syncthreads();
        gv = gv_next;
    }

    // final c_s[Ns-1] on hs[Ns-1]
    if (!is_gate) {
        const ulonglong2* hv = reinterpret_cast<const ulonglong2*>(h_sh);
        u64t a0 = 0ULL, a1 = 0ULL, a2 = 0ULL, a3 = 0ULL;
        #pragma unroll
        for (int p = 0; p < 16; p++) {
            ulonglong2 h4 = hv[p];
            if (p & 1) { a2 = ffma2(wr[2*p], h4.x, a2); a3 = ffma2(wr[2*p+1], h4.y, a3); }
            else       { a0 = ffma2(wr[2*p], h4.x, a0); a1 = ffma2(wr[2*p+1], h4.y, a1); }
        }
        csb[(size_t)(Ns - 1) * 32 + (j - 192)] =
            hsum2(fadd2(fadd2(a0, a1), fadd2(a2, a3))) + bj;
    }
}

// =====================================================================
// Kernel C (R4 form, verified 144us): fast path, 2 consecutive frames per
// thread (share 16 x-samples). Per jj: 24 broadcast LDS.128 feed 96 FFMA2.
// =====================================================================
__global__ void __launch_bounds__(128) fast_kernel(const float* __restrict__ x,
                                                   const float* __restrict__ W1,
                                                   const float* __restrict__ b1,
                                                   const float* __restrict__ W2,
                                                   const float* __restrict__ b2,
                                                   int T, int Nf, int Ns) {
    __shared__ __align__(16) float W1sh[64 * 64];   // [j][k]
    __shared__ __align__(16) float W2T[64 * 32];    // [j][i]
    __shared__ float b1sh[64];
    __shared__ u64t  b2sh[16];

    const int b   = blockIdx.y;
    const int tid = threadIdx.x;
    const int n0  = (blockIdx.x * 128 + tid) * 2;
    const int n1  = n0 + 1;

    for (int i = tid; i < 4096; i += 128) W1sh[i] = W1[i];
    for (int i = tid; i < 2048; i += 128) { int jj = i >> 5, ii = i & 31; W2T[i] = W2[ii * 64 + jj]; }
    if (tid < 64) b1sh[tid] = b1[tid];
    if (tid < 16) b2sh[tid] = fpack2(b2[2 * tid], b2[2 * tid + 1]);
    __syncthreads();

    if (n0 >= Nf) return;
    const bool v1 = (n1 < Nf);

    u64t xf[24];
    {
        const float4* xp = reinterpret_cast<const float4*>(x + (size_t)b * T + (size_t)n0 * 16);
        #pragma unroll
        for (int q = 0; q < 12; q++) {
            float4 v = (q < 8 || v1) ? xp[q] : make_float4(0.f, 0.f, 0.f, 0.f);
            xf[2*q]   = fpack2(v.x, v.y);
            xf[2*q+1] = fpack2(v.z, v.w);
        }
    }
    u64t cf0[16], cf1[16];
    {
        int cn0 = n0 / 3 - 1; if (cn0 < 0) cn0 = 0;
        int cn1 = v1 ? (n1 / 3 - 1) : cn0; if (cn1 < 0) cn1 = 0;
        const ulonglong2* cp0 = reinterpret_cast<const ulonglong2*>(g_cs + ((size_t)b * Ns + cn0) * 32);
        const ulonglong2* cp1 = reinterpret_cast<const ulonglong2*>(g_cs + ((size_t)b * Ns + cn1) * 32);
        #pragma unroll
        for (int q = 0; q < 8; q++) {
            ulonglong2 u = cp0[q]; cf0[2*q] = u.x; cf0[2*q+1] = u.y;
            ulonglong2 w = cp1[q]; cf1[2*q] = w.x; cf1[2*q+1] = w.y;
        }
    }

    u64t ya[16], yb[16];
    #pragma unroll
    for (int i = 0; i < 16; i++) { ya[i] = 0ULL; yb[i] = 0ULL; }

    #pragma unroll 1
    for (int jj = 0; jj < 64; jj++) {
        const ulonglong2* w1v = reinterpret_cast<const ulonglong2*>(&W1sh[jj * 64]);
        u64t a0=0ULL,a1=0ULL,a2=0ULL,a3=0ULL;
        u64t c0=0ULL,c1=0ULL,c2=0ULL,c3=0ULL;
        #pragma unroll
        for (int p = 0; p < 8; p++) {
            ulonglong2 w = w1v[p];
            a0 = ffma2(w.x, xf[2*p],   a0); a1 = ffma2(w.y, xf[2*p+1],   a1);
            c0 = ffma2(w.x, xf[8+2*p], c0); c1 = ffma2(w.y, xf[8+2*p+1], c1);
        }
        #pragma unroll
        for (int p = 0; p < 8; p++) {
            ulonglong2 w = w1v[8 + p];
            a2 = ffma2(w.x, cf0[2*p], a2); a3 = ffma2(w.y, cf0[2*p+1], a3);
            c2 = ffma2(w.x, cf1[2*p], c2); c3 = ffma2(w.y, cf1[2*p+1], c3);
        }
        float hA = fmaxf(hsum2(fadd2(fadd2(a0,a1), fadd2(a2,a3))) + b1sh[jj], 0.f);
        float hB = fmaxf(hsum2(fadd2(fadd2(c0,c1), fadd2(c2,c3))) + b1sh[jj], 0.f);
        u64t hA2 = fpack2(hA, hA);
        u64t hB2 = fpack2(hB, hB);
        const ulonglong2* w2v = reinterpret_cast<const ulonglong2*>(&W2T[jj * 32]);
        #pragma unroll
        for (int p = 0; p < 8; p++) {
            ulonglong2 w = w2v[p];
            ya[2*p] = ffma2(w.x, hA2, ya[2*p]); ya[2*p+1] = ffma2(w.y, hA2, ya[2*p+1]);
            yb[2*p] = ffma2(w.x, hB2, yb[2*p]); yb[2*p+1] = ffma2(w.y, hB2, yb[2*p+1]);
        }
    }

    {
        float4* yo = reinterpret_cast<float4*>(&g_y[((size_t)b * Nf + n0) * 32]);
        #pragma unroll
        for (int p = 0; p < 8; p++) {
            float2 va = funpack2(fadd2(ya[2*p],     b2sh[2*p]));
            float2 vb = funpack2(fadd2(ya[2*p + 1], b2sh[2*p + 1]));
            yo[p] = make_float4(va.x, va.y, vb.x, vb.y);
        }
        if (v1) {
            float4* yo1 = reinterpret_cast<float4*>(&g_y[((size_t)b * Nf + n1) * 32]);
            #pragma unroll
            for (int p = 0; p < 8; p++) {
                float2 va = funpack2(fadd2(yb[2*p],     b2sh[2*p]));
                float2 vb = funpack2(fadd2(yb[2*p + 1], b2sh[2*p + 1]));
                yo1[p] = make_float4(va.x, va.y, vb.x, vb.y);
            }
        }
    }
}

// =====================================================================
// Kernel D: overlap-add as gather (each sample covered by <=2 frames).
// =====================================================================
__global__ void __launch_bounds__(256) gather_kernel(float* __restrict__ out,
                                                     int T, int Nf) {
    const int idx = blockIdx.x * blockDim.x + threadIdx.x;
    const int total = BSZ * T;
    if (idx >= total) return;
    const int b = idx / T, t = idx % T;
    const int n0 = t >> 4, r = t & 15;
    const float* yb = g_y + (size_t)b * Nf * 32;
    float v = 0.f;
    if (n0 < Nf)                 v += yb[n0 * 32 + r];
    if (n0 >= 1 && n0 - 1 < Nf)  v += yb[(n0 - 1) * 32 + 16 + r];
    out[idx] = v;
}

// =====================================================================
extern "C" void kernel_launch(void* const* d_in, const int* in_sizes, int n_in,
                              void* d_out, int out_size) {
    const float* x    = (const float*)d_in[0];
    const float* W_ih = (const float*)d_in[1];
    const float* W_hh = (const float*)d_in[2];
    const float* b_ih = (const float*)d_in[3];
    const float* b_hh = (const float*)d_in[4];
    const float* W_cs = (const float*)d_in[5];
    const float* b_cs = (const float*)d_in[6];
    const float* W1   = (const float*)d_in[7];
    const float* b1   = (const float*)d_in[8];
    const float* W2   = (const float*)d_in[9];
    const float* b2   = (const float*)d_in[10];
    float* out = (float*)d_out;

    const int T  = in_sizes[0] / BSZ;
    const int Nf = (T - 32) / 16 + 1;
    const int Ns = (T - 96) / 48 + 1;

    gi_kernel    <<<dim3((Ns + 127) / 128, BSZ), 128>>>(x, W_ih, b_ih, T, Ns);
    gru_kernel   <<<BSZ, 224>>>(W_hh, b_hh, W_cs, b_cs, Ns);
    fast_kernel  <<<dim3((Nf + 255) / 256, BSZ), 128>>>(x, W1, b1, W2, b2, T, Nf, Ns);
    gather_kernel<<<(BSZ * T + 255) / 256, 256>>>(out, T, Nf);
}